// round 7
// baseline (speedup 1.0000x reference)
#include <cuda_runtime.h>
#include <stdint.h>
#include <math.h>

#define DIM 256
#define NGATES 46
#define NROWS 32768

// GEMM tiling
#define BM 128
#define BN 256
#define NCHUNK 12            // per N-pass: 4 hh + 4 ab + 4 ba (64B k-chunks)
#define THREADS 512
#define PITCH 80             // smem row pitch (bytes): 5x16B units, coprime 8 -> ldsm conflict-free

#define A_STAGE (BM * PITCH)           // 10240
#define B_STAGE (BN * PITCH)           // 20480
#define STAGE (A_STAGE + B_STAGE)      // 30720
#define TS_OFF (3 * STAGE)             // 92160
#define YPART_OFF (TS_OFF + 2048)      // 94208  float[4][128][8]
#define YOUT_OFF (YPART_OFF + 16384)   // 110592 float[128][8]
#define SMEM_TOTAL (YOUT_OFF + 4096)   // 114688

// Scratch (device globals — no allocation)
__device__ __align__(16) int8_t g_Xq[(size_t)NROWS * 512];  // [row][a(256) | b(256)]
__device__ __align__(16) int8_t g_Wq[512 * 512];            // [c][a(256) | b(256)]
__device__ float g_Wf[512 * 256];                           // [c][d] fp32 W
__device__ float g_ts[512];                                 // t_c * 2^-21

struct Cplx { float x, y; };
__device__ __forceinline__ Cplx cmul(Cplx a, Cplx b) { return {a.x*b.x - a.y*b.y, a.x*b.y + a.y*b.x}; }
__device__ __forceinline__ Cplx cadd(Cplx a, Cplx b) { return {a.x + b.x, a.y + b.y}; }

__device__ __forceinline__ uint32_t pack4(int a0, int a1, int a2, int a3) {
    return (uint32_t)(a0 & 255) | ((uint32_t)(a1 & 255) << 8) |
           ((uint32_t)(a2 & 255) << 16) | ((uint32_t)(a3 & 255) << 24);
}

// ---------------- fused: build_U (blocks 0-255, fp32 W out) + prep_x quantize ----------------
__global__ void prep_build_kernel(const float* __restrict__ x,
                                  const float* __restrict__ th1,
                                  const float* __restrict__ th2,
                                  const float* __restrict__ th3) {
    const int tid = threadIdx.x;
    if (blockIdx.x < 256) {
        __shared__ float2 s[DIM];
        __shared__ Cplx M[NGATES][4];
        const int col = blockIdx.x;   // basis state d

        if (tid < NGATES) {
            int g = tid, a, r;
            if (g < 16)      { a = 0; r = g; }
            else if (g < 30) { a = 1; r = g - 16; }
            else             { a = 2; r = g - 30; }
            const float* th = (a == 0) ? th1 : ((a == 1) ? th2 : th3);
            float t1 = th[r*3 + 0], t2 = th[r*3 + 1], t3 = th[r*3 + 2];
            float cx, sx, cy, sy, cz, szv;
            sincosf(0.5f * t1, &sx, &cx);
            sincosf(0.5f * t2, &sy, &cy);
            sincosf(0.5f * t3, &szv, &cz);
            Cplx A00 = { cy*cx,  sy*sx};
            Cplx A01 = {-sy*cx, -cy*sx};
            Cplx A10 = { sy*cx, -cy*sx};
            Cplx A11 = { cy*cx, -sy*sx};
            Cplx em = {cz, -szv}, ep = {cz, szv};
            M[tid][0] = cmul(em, A00);
            M[tid][1] = cmul(em, A01);
            M[tid][2] = cmul(ep, A10);
            M[tid][3] = cmul(ep, A11);
        }
        if (tid < 128)
            for (int k = tid; k < DIM; k += 128)
                s[k] = make_float2(k == col ? 1.0f : 0.0f, 0.0f);
        __syncthreads();

        const int nqs[3] = {8, 7, 8};
        int g = 0;
        for (int a = 0; a < 3; a++) {
            const int nq = nqs[a];
            for (int d = 0; d < 2; d++) {
                for (int q = 0; q < nq; q++) {
                    if (tid < 128) {
                        Cplx m00 = M[g][0], m01 = M[g][1], m10 = M[g][2], m11 = M[g][3];
                        int p = tid;
                        int i0 = ((p >> q) << (q + 1)) | (p & ((1 << q) - 1));
                        int i1 = i0 | (1 << q);
                        float2 a0 = s[i0], a1 = s[i1];
                        Cplx ca0 = {a0.x, a0.y}, ca1 = {a1.x, a1.y};
                        Cplx n0 = cadd(cmul(m00, ca0), cmul(m01, ca1));
                        Cplx n1 = cadd(cmul(m10, ca0), cmul(m11, ca1));
                        s[i0] = make_float2(n0.x, n0.y);
                        s[i1] = make_float2(n1.x, n1.y);
                    }
                    g++;
                    __syncthreads();
                }
                for (int q = 0; q < nq - 1; q++) {
                    if (tid < 64) {
                        int m = tid;
                        int base = ((m >> q) << (q + 2)) | (m & ((1 << q) - 1));
                        int i0 = base | (1 << q);
                        int i1 = i0 | (2 << q);
                        float2 t = s[i0]; s[i0] = s[i1]; s[i1] = t;
                    }
                    __syncthreads();
                }
            }
        }
        // W[c=k][d=col] = Re U[k][col], W[256+k][col] = Im U[k][col]
        if (tid < 128)
            for (int k = tid; k < DIM; k += 128) {
                g_Wf[(size_t)k * 256 + col]        = s[k].x;
                g_Wf[(size_t)(256 + k) * 256 + col] = s[k].y;
            }
    } else {
        // ---- prep_x: 8 warps, one row each; per-row max-abs scale, two-level int8 ----
        const int wid = tid >> 5, l = tid & 31;
        const int row = (blockIdx.x - 256) * 8 + wid;
        const float4* xr = reinterpret_cast<const float4*>(x + (size_t)row * 256);
        float4 v1 = xr[l], v2 = xr[l + 32];
        float m = fmaxf(fmaxf(fmaxf(fabsf(v1.x), fabsf(v1.y)), fmaxf(fabsf(v1.z), fabsf(v1.w))),
                        fmaxf(fmaxf(fabsf(v2.x), fabsf(v2.y)), fmaxf(fabsf(v2.z), fabsf(v2.w))));
#pragma unroll
        for (int off = 16; off; off >>= 1)
            m = fmaxf(m, __shfl_xor_sync(0xffffffffu, m, off));
        float inv = (m > 0.f) ? (127.f / m) : 0.f;

        uint32_t* dst = reinterpret_cast<uint32_t*>(g_Xq) + (size_t)row * 128;
#pragma unroll
        for (int p = 0; p < 2; p++) {
            float f[4];
            if (p == 0) { f[0]=v1.x; f[1]=v1.y; f[2]=v1.z; f[3]=v1.w; }
            else        { f[0]=v2.x; f[1]=v2.y; f[2]=v2.z; f[3]=v2.w; }
            int ia[4], ib[4];
#pragma unroll
            for (int i = 0; i < 4; i++) {
                float q = f[i] * inv;
                ia[i] = __float2int_rn(q);
                ib[i] = __float2int_rn((q - (float)ia[i]) * 128.f);
            }
            dst[p * 32 + l]      = pack4(ia[0], ia[1], ia[2], ia[3]);
            dst[64 + p * 32 + l] = pack4(ib[0], ib[1], ib[2], ib[3]);
        }
    }
}

// ---------------- quantize W columns ----------------
__global__ void quant_w_kernel() {
    const int wid = threadIdx.x >> 5, l = threadIdx.x & 31;
    const int c = blockIdx.x * 4 + wid;           // grid 128 x 128thr -> 512 cols
    const float4* wr = reinterpret_cast<const float4*>(g_Wf + (size_t)c * 256);
    float4 v1 = wr[l], v2 = wr[l + 32];
    float m = fmaxf(fmaxf(fmaxf(fabsf(v1.x), fabsf(v1.y)), fmaxf(fabsf(v1.z), fabsf(v1.w))),
                    fmaxf(fmaxf(fabsf(v2.x), fabsf(v2.y)), fmaxf(fabsf(v2.z), fabsf(v2.w))));
#pragma unroll
    for (int off = 16; off; off >>= 1)
        m = fmaxf(m, __shfl_xor_sync(0xffffffffu, m, off));
    float inv = (m > 0.f) ? (127.f / m) : 0.f;
    if (l == 0)
        g_ts[c] = (m > 0.f) ? (m * (128.f / 127.f)) * (1.f / 2097152.f) : 0.f;  // t_c * 2^-21

    uint32_t* dst = reinterpret_cast<uint32_t*>(g_Wq) + (size_t)c * 128;
#pragma unroll
    for (int p = 0; p < 2; p++) {
        float f[4];
        if (p == 0) { f[0]=v1.x; f[1]=v1.y; f[2]=v1.z; f[3]=v1.w; }
        else        { f[0]=v2.x; f[1]=v2.y; f[2]=v2.z; f[3]=v2.w; }
        int ia[4], ib[4];
#pragma unroll
        for (int i = 0; i < 4; i++) {
            float q = f[i] * inv;
            ia[i] = __float2int_rn(q);
            ib[i] = __float2int_rn((q - (float)ia[i]) * 128.f);
        }
        dst[p * 32 + l]      = pack4(ia[0], ia[1], ia[2], ia[3]);
        dst[64 + p * 32 + l] = pack4(ib[0], ib[1], ib[2], ib[3]);
    }
}

// ---------------- IMMA GEMM + epilogue ----------------
__device__ __forceinline__ void cpa16(unsigned int d, const void* s) {
    asm volatile("cp.async.cg.shared.global [%0], [%1], 16;\n" :: "r"(d), "l"(s));
}
#define CP_COMMIT() asm volatile("cp.async.commit_group;\n" ::: "memory")
#define CP_WAIT(N)  asm volatile("cp.async.wait_group %0;\n" :: "n"(N) : "memory")

#define LDSM4(R0,R1,R2,R3,ADDR) \
    asm volatile("ldmatrix.sync.aligned.m8n8.x4.shared.b16 {%0,%1,%2,%3}, [%4];" \
        : "=r"(R0), "=r"(R1), "=r"(R2), "=r"(R3) : "r"(ADDR))

#define IMMA16832(C, A, B0, B1) \
    asm volatile("mma.sync.aligned.m16n8k32.row.col.s32.s8.s8.s32 " \
        "{%0,%1,%2,%3},{%4,%5,%6,%7},{%8,%9},{%0,%1,%2,%3};" \
        : "+r"((C)[0]), "+r"((C)[1]), "+r"((C)[2]), "+r"((C)[3]) \
        : "r"((A)[0]), "r"((A)[1]), "r"((A)[2]), "r"((A)[3]), "r"(B0), "r"(B1))

// chunk ci (per pass): 0-3 hh (X.a x W.a), 4-7 (X.a x W.b), 8-11 (X.b x W.a)
__device__ __forceinline__ void load_chunk(unsigned int sbase, int tid, int ci, int row0, int n0) {
    const int buf = ci % 3;
    const int xoff = (ci < 8) ? ((ci & 3) * 64) : (256 + (ci - 8) * 64);
    const int woff = (ci < 4) ? (ci * 64) : ((ci < 8) ? (256 + (ci - 4) * 64) : ((ci - 8) * 64));
    unsigned int sA = sbase + buf * STAGE;
    unsigned int sB = sA + A_STAGE;
    {   // A: 128 rows x 4x16B
        int r = tid >> 2, ch = tid & 3;
        cpa16(sA + r * PITCH + ch * 16,
              &g_Xq[(size_t)(row0 + r) * 512 + xoff + ch * 16]);
    }
#pragma unroll
    for (int p = 0; p < 2; p++) {   // B: 256 cols x 4x16B
        int u = tid + p * THREADS;
        int r = u >> 2, ch = u & 3;
        cpa16(sB + r * PITCH + ch * 16,
              &g_Wq[(size_t)(n0 + r) * 512 + woff + ch * 16]);
    }
    CP_COMMIT();
}

__global__ __launch_bounds__(THREADS, 1)
void pqc_imma_kernel(float* __restrict__ out) {
    extern __shared__ __align__(16) char smem[];
    float* ts_sm = reinterpret_cast<float*>(smem + TS_OFF);   // [512]
    float* ypart = reinterpret_cast<float*>(smem + YPART_OFF);
    float* yout  = reinterpret_cast<float*>(smem + YOUT_OFF);

    const int tid = threadIdx.x;
    const int l = tid & 31;
    const int wid = tid >> 5;
    const int wm = wid & 3;        // 32-row group
    const int wn = wid >> 2;       // 64-col group
    const int row0 = blockIdx.x * BM;

    unsigned int sbase;
    asm("{ .reg .u64 t; cvta.to.shared.u64 t, %1; cvt.u32.u64 %0, t; }" : "=r"(sbase) : "l"(smem));

    ts_sm[tid] = g_ts[tid];

    for (int nc = 0; nc < 2; nc++) {
        const int n0 = nc * BN;
        int acc[2][8][4];
#pragma unroll
        for (int mt = 0; mt < 2; mt++)
#pragma unroll
            for (int nt = 0; nt < 8; nt++)
#pragma unroll
                for (int e = 0; e < 4; e++) acc[mt][nt][e] = 0;

        load_chunk(sbase, tid, 0, row0, n0);
        load_chunk(sbase, tid, 1, row0, n0);

        for (int ci = 0; ci < NCHUNK; ci++) {
            if (ci < NCHUNK - 1) { CP_WAIT(1); } else { CP_WAIT(0); }
            __syncthreads();
            if (ci + 2 < NCHUNK) load_chunk(sbase, tid, ci + 2, row0, n0);

            unsigned int aBase = sbase + (ci % 3) * STAGE;
            unsigned int bBase = aBase + A_STAGE;
#pragma unroll
            for (int s = 0; s < 2; s++) {
                unsigned int a[2][4], b[4][4];
#pragma unroll
                for (int mt = 0; mt < 2; mt++) {
                    unsigned int addr = aBase + (wm*32 + mt*16 + (l & 15)) * PITCH
                                      + (l >> 4) * 16 + s * 32;
                    LDSM4(a[mt][0], a[mt][1], a[mt][2], a[mt][3], addr);
                }
#pragma unroll
                for (int bn = 0; bn < 4; bn++) {
                    unsigned int addr = bBase
                        + (wn*64 + bn*16 + (l & 7) + ((l >> 4) & 1) * 8) * PITCH
                        + ((l >> 3) & 1) * 16 + s * 32;
                    LDSM4(b[bn][0], b[bn][1], b[bn][2], b[bn][3], addr);
                }
#pragma unroll
                for (int mt = 0; mt < 2; mt++)
#pragma unroll
                    for (int nt = 0; nt < 8; nt++)
                        IMMA16832(acc[mt][nt], a[mt],
                                  b[nt >> 1][(nt & 1) * 2], b[nt >> 1][(nt & 1) * 2 + 1]);
            }
            if (ci == 3) {   // hh done: pre-scale by 128 before cross terms
#pragma unroll
                for (int mt = 0; mt < 2; mt++)
#pragma unroll
                    for (int nt = 0; nt < 8; nt++)
#pragma unroll
                        for (int e = 0; e < 4; e++) acc[mt][nt][e] <<= 7;
            }
        }

        // ---- epilogue: z = ts[c] * acc (row scale cancels); sign-weighted |z|^2 -> y[8]
        // col c = n0 + wn*64 + nt*8 + 2*(l&3) + e ; k = c & 255
        // k bits: b0=e(j7), b1..2=l&3(j6,j5), b3..5=nt(j4,j3,j2), b6=wn&1(j1), b7=wn>>1(j0)
        float tv0[8], tv1[8];
#pragma unroll
        for (int nt = 0; nt < 8; nt++) {
            int cbase = n0 + wn * 64 + nt * 8 + 2 * (l & 3);
            tv0[nt] = ts_sm[cbase];
            tv1[nt] = ts_sm[cbase + 1];
        }
        float yp[2][2][8];
#pragma unroll
        for (int mt = 0; mt < 2; mt++) {
#pragma unroll
            for (int half = 0; half < 2; half++) {
                float s0 = 0.f, T7 = 0.f, T4 = 0.f, T3 = 0.f, T2 = 0.f;
#pragma unroll
                for (int nt = 0; nt < 8; nt++) {
                    float v0 = __int2float_rn(acc[mt][nt][2 * half])     * tv0[nt];
                    float v1 = __int2float_rn(acc[mt][nt][2 * half + 1]) * tv1[nt];
                    float p1 = v1 * v1;
                    float ps = v0 * v0 + p1;
                    s0 += ps; T7 += p1;
                    if (nt & 1) T4 += ps;
                    if (nt & 2) T3 += ps;
                    if (nt & 4) T2 += ps;
                }
                yp[mt][half][7] = s0 - 2.f * T7;
                yp[mt][half][4] = s0 - 2.f * T4;
                yp[mt][half][3] = s0 - 2.f * T3;
                yp[mt][half][2] = s0 - 2.f * T2;
                yp[mt][half][6] = (l & 1) ? -s0 : s0;
                yp[mt][half][5] = (l & 2) ? -s0 : s0;
                yp[mt][half][1] = (wn & 1) ? -s0 : s0;
                yp[mt][half][0] = (wn & 2) ? -s0 : s0;
            }
        }
#pragma unroll
        for (int off = 1; off <= 2; off <<= 1)
#pragma unroll
            for (int mt = 0; mt < 2; mt++)
#pragma unroll
                for (int half = 0; half < 2; half++)
#pragma unroll
                    for (int ob = 0; ob < 8; ob++)
                        yp[mt][half][ob] += __shfl_xor_sync(0xffffffffu, yp[mt][half][ob], off);

        if ((l & 3) == 0) {
#pragma unroll
            for (int mt = 0; mt < 2; mt++)
#pragma unroll
                for (int half = 0; half < 2; half++) {
                    int r = wm * 32 + mt * 16 + half * 8 + (l >> 2);
                    float* dst = &ypart[((size_t)wn * BM + r) * 8];
                    if (nc == 0) {
#pragma unroll
                        for (int ob = 0; ob < 8; ob++) dst[ob] = yp[mt][half][ob];
                    } else {
#pragma unroll
                        for (int ob = 0; ob < 8; ob++) dst[ob] += yp[mt][half][ob];
                    }
                }
        }
        __syncthreads();
    }

    // reduce over wn partials
    for (int idx = tid; idx < BM * 8; idx += THREADS) {
        yout[idx] = ypart[idx] + ypart[BM * 8 + idx]
                  + ypart[2 * BM * 8 + idx] + ypart[3 * BM * 8 + idx];
    }
    __syncthreads();

    if (tid < 128) {
        float yv[8], n2 = 0.f;
#pragma unroll
        for (int ob = 0; ob < 8; ob++) { yv[ob] = yout[tid * 8 + ob]; n2 += yv[ob] * yv[ob]; }
        float inv = 1.0f / fmaxf(n2, 1e-30f);
#pragma unroll
        for (int ob = 0; ob < 8; ob++) yout[tid * 8 + ob] = yv[ob] * yv[ob] * inv;
    }
    __syncthreads();

    // coalesced output: 128 rows x 64 float4 (only first 8 floats nonzero)
#pragma unroll
    for (int i = 0; i < 16; i++) {
        int idx = tid + i * THREADS;
        int rr = idx >> 6, q = idx & 63;
        float4 v = make_float4(0.f, 0.f, 0.f, 0.f);
        if (q == 0) v = *reinterpret_cast<float4*>(&yout[rr * 8]);
        else if (q == 1) v = *reinterpret_cast<float4*>(&yout[rr * 8 + 4]);
        reinterpret_cast<float4*>(out + (size_t)(row0 + rr) * 256)[q] = v;
    }
}

extern "C" void kernel_launch(void* const* d_in, const int* in_sizes, int n_in,
                              void* d_out, int out_size) {
    const float* x   = (const float*)d_in[0];
    const float* th1 = (const float*)d_in[1];
    const float* th2 = (const float*)d_in[2];
    const float* th3 = (const float*)d_in[3];
    float* out = (float*)d_out;

    int nrows = in_sizes[0] / 256;   // 32768

    cudaFuncSetAttribute(pqc_imma_kernel,
                         cudaFuncAttributeMaxDynamicSharedMemorySize, SMEM_TOTAL);

    prep_build_kernel<<<256 + nrows / 8, 256>>>(x, th1, th2, th3);
    quant_w_kernel<<<128, 128>>>();
    pqc_imma_kernel<<<nrows / BM, THREADS, SMEM_TOTAL>>>(out);
}

// round 8
// speedup vs baseline: 2.6311x; 2.6311x over previous
#include <cuda_runtime.h>
#include <cuda_fp16.h>
#include <stdint.h>
#include <math.h>

#define DIM 256
#define NGATES 46
#define NROWS 32768
#define BM 128
#define BN 256
#define KC 64
#define NCH 8                // 4 chunks X*vh + 4 chunks X*vl
#define THREADS 512
#define STAGES 3
#define APITCH 72            // 64 + 8 pad (fp16 elems)
#define AS_BYTES (BM * APITCH * 2)    // 18432
#define BS_BYTES (BN * APITCH * 2)    // 36864
#define SMEM_YPART_OFF (STAGES * (AS_BYTES + BS_BYTES))           // 165888
#define SMEM_YS_OFF (SMEM_YPART_OFF + 4 * BM * 8 * 4)             // +16384
#define SMEM_TOTAL (SMEM_YS_OFF + BM * 8 * 4)                     // 186368

// Scratch (device globals — no allocation)
__device__ __half g_Xh[(size_t)NROWS * 256];   // [row][d]  fp16(x)
__device__ __half g_Wcat[512 * 512];           // [c][ vh(256) | vl(256) ],  V = 128*W

struct Cplx { float x, y; };
__device__ __forceinline__ Cplx cmul(Cplx a, Cplx b) { return {a.x*b.x - a.y*b.y, a.x*b.y + a.y*b.x}; }
__device__ __forceinline__ Cplx cadd(Cplx a, Cplx b) { return {a.x + b.x, a.y + b.y}; }

// ---------------- fused: build_U (blocks 0-255) + prep_x (rest) ----------------
__global__ void prep_build_kernel(const float* __restrict__ x,
                                  const float* __restrict__ th1,
                                  const float* __restrict__ th2,
                                  const float* __restrict__ th3) {
    const int tid = threadIdx.x;
    if (blockIdx.x < 256) {
        __shared__ float2 s[DIM];
        __shared__ Cplx M[NGATES][4];
        const int col = blockIdx.x;   // basis state d

        if (tid < NGATES) {
            int g = tid, a, r;
            if (g < 16)      { a = 0; r = g; }
            else if (g < 30) { a = 1; r = g - 16; }
            else             { a = 2; r = g - 30; }
            const float* th = (a == 0) ? th1 : ((a == 1) ? th2 : th3);
            float t1 = th[r*3 + 0], t2 = th[r*3 + 1], t3 = th[r*3 + 2];
            float cx, sx, cy, sy, cz, szv;
            sincosf(0.5f * t1, &sx, &cx);
            sincosf(0.5f * t2, &sy, &cy);
            sincosf(0.5f * t3, &szv, &cz);
            Cplx A00 = { cy*cx,  sy*sx};
            Cplx A01 = {-sy*cx, -cy*sx};
            Cplx A10 = { sy*cx, -cy*sx};
            Cplx A11 = { cy*cx, -sy*sx};
            Cplx em = {cz, -szv}, ep = {cz, szv};
            M[tid][0] = cmul(em, A00);
            M[tid][1] = cmul(em, A01);
            M[tid][2] = cmul(ep, A10);
            M[tid][3] = cmul(ep, A11);
        }
        if (tid < 128)
            for (int k = tid; k < DIM; k += 128)
                s[k] = make_float2(k == col ? 1.0f : 0.0f, 0.0f);
        __syncthreads();

        const int nqs[3] = {8, 7, 8};
        int g = 0;
        for (int a = 0; a < 3; a++) {
            const int nq = nqs[a];
            for (int d = 0; d < 2; d++) {
                for (int q = 0; q < nq; q++) {
                    if (tid < 128) {
                        Cplx m00 = M[g][0], m01 = M[g][1], m10 = M[g][2], m11 = M[g][3];
                        int p = tid;
                        int i0 = ((p >> q) << (q + 1)) | (p & ((1 << q) - 1));
                        int i1 = i0 | (1 << q);
                        float2 a0 = s[i0], a1 = s[i1];
                        Cplx ca0 = {a0.x, a0.y}, ca1 = {a1.x, a1.y};
                        Cplx n0 = cadd(cmul(m00, ca0), cmul(m01, ca1));
                        Cplx n1 = cadd(cmul(m10, ca0), cmul(m11, ca1));
                        s[i0] = make_float2(n0.x, n0.y);
                        s[i1] = make_float2(n1.x, n1.y);
                    }
                    g++;
                    __syncthreads();
                }
                for (int q = 0; q < nq - 1; q++) {
                    if (tid < 64) {
                        int m = tid;
                        int base = ((m >> q) << (q + 2)) | (m & ((1 << q) - 1));
                        int i0 = base | (1 << q);
                        int i1 = i0 | (2 << q);
                        float2 t = s[i0]; s[i0] = s[i1]; s[i1] = t;
                    }
                    __syncthreads();
                }
            }
        }
        // W[c=k][col] = Re U[k][col], W[256+k][col] = Im. Store V=128*W split hi/lo fp16.
        if (tid < 128)
            for (int k = tid; k < DIM; k += 128) {
                float vr = s[k].x * 128.f, vi = s[k].y * 128.f;
                __half rh = __float2half_rn(vr);
                __half rl = __float2half_rn(vr - __half2float(rh));
                __half ih = __float2half_rn(vi);
                __half il = __float2half_rn(vi - __half2float(ih));
                g_Wcat[(size_t)k * 512 + col]               = rh;
                g_Wcat[(size_t)k * 512 + 256 + col]         = rl;
                g_Wcat[(size_t)(256 + k) * 512 + col]       = ih;
                g_Wcat[(size_t)(256 + k) * 512 + 256 + col] = il;
            }
    } else {
        // ---- prep_x: one float4 -> 4 fp16 per thread ----
        int idx = (blockIdx.x - 256) * 256 + tid;
        int row = idx >> 6;
        int q = idx & 63;
        float4 v = reinterpret_cast<const float4*>(x)[idx];
        __half2 h0 = __floats2half2_rn(v.x, v.y);
        __half2 h1 = __floats2half2_rn(v.z, v.w);
        __half2* p = reinterpret_cast<__half2*>(&g_Xh[(size_t)row * 256 + q * 4]);
        p[0] = h0;
        p[1] = h1;
    }
}

// ---------------- GEMM + epilogue ----------------
__device__ __forceinline__ void cpa16(unsigned int d, const void* s) {
    asm volatile("cp.async.cg.shared.global [%0], [%1], 16;\n" :: "r"(d), "l"(s));
}
#define CP_COMMIT() asm volatile("cp.async.commit_group;\n" ::: "memory")
#define CP_WAIT(N)  asm volatile("cp.async.wait_group %0;\n" :: "n"(N) : "memory")

#define LDSM4(R0,R1,R2,R3,ADDR) \
    asm volatile("ldmatrix.sync.aligned.m8n8.x4.shared.b16 {%0,%1,%2,%3}, [%4];" \
        : "=r"(R0), "=r"(R1), "=r"(R2), "=r"(R3) : "r"(ADDR))

#define MMA16816(C, A, B0, B1) \
    asm volatile("mma.sync.aligned.m16n8k16.row.col.f32.f16.f16.f32 " \
        "{%0,%1,%2,%3},{%4,%5,%6,%7},{%8,%9},{%0,%1,%2,%3};" \
        : "+f"((C)[0]), "+f"((C)[1]), "+f"((C)[2]), "+f"((C)[3]) \
        : "r"((A)[0]), "r"((A)[1]), "r"((A)[2]), "r"((A)[3]), "r"(B0), "r"(B1))

// chunks 0-3: X[k] x vh[k];  chunks 4-7: X[k] x vl[k]  (k-slice = (ci&3)*64)
__device__ __forceinline__ void load_chunk(char* smem, int tid, int buf, int ci,
                                           int row0, int n0) {
    const int srcA = (ci & 3) * KC;
    const int woff = ci * KC;
    unsigned int sA = (unsigned int)__cvta_generic_to_shared(smem) + buf * (AS_BYTES + BS_BYTES);
    unsigned int sB = sA + AS_BYTES;
#pragma unroll
    for (int p = 0; p < 2; p++) {
        int u = tid + p * THREADS;
        int r = u >> 3, ch = u & 7;
        cpa16(sA + (r * APITCH + ch * 8) * 2,
              &g_Xh[(size_t)(row0 + r) * 256 + srcA + ch * 8]);
    }
#pragma unroll
    for (int p = 0; p < 4; p++) {
        int u = tid + p * THREADS;
        int r = u >> 3, ch = u & 7;
        cpa16(sB + (r * APITCH + ch * 8) * 2,
              &g_Wcat[(size_t)(n0 + r) * 512 + woff + ch * 8]);
    }
    CP_COMMIT();
}

__global__ __launch_bounds__(THREADS, 1)
void pqc_mma_kernel(float* __restrict__ out) {
    extern __shared__ char smem[];
    float* ypart = reinterpret_cast<float*>(smem + SMEM_YPART_OFF);  // [4][128][8]
    float* ys    = reinterpret_cast<float*>(smem + SMEM_YS_OFF);     // [128][8]

    const int tid = threadIdx.x;
    const int l = tid & 31;
    const int wid = tid >> 5;
    const int wm = wid & 3;        // row group (32 rows)
    const int wn = wid >> 2;       // col group (64 cols)
    const int row0 = blockIdx.x * BM;

    const unsigned int smem_u32 = (unsigned int)__cvta_generic_to_shared(smem);

    for (int nc = 0; nc < 2; nc++) {
        const int n0 = nc * BN;
        float acc[2][8][4];
#pragma unroll
        for (int mt = 0; mt < 2; mt++)
#pragma unroll
            for (int nt = 0; nt < 8; nt++)
#pragma unroll
                for (int e = 0; e < 4; e++) acc[mt][nt][e] = 0.0f;

        load_chunk(smem, tid, 0, 0, row0, n0);
        load_chunk(smem, tid, 1, 1, row0, n0);

        for (int ci = 0; ci < NCH; ci++) {
            int buf = ci % STAGES;
            if (ci + STAGES - 1 < NCH)
                load_chunk(smem, tid, (ci + STAGES - 1) % STAGES, ci + STAGES - 1, row0, n0);
            if (ci < NCH - 2)      { CP_WAIT(2); }
            else if (ci == NCH - 2){ CP_WAIT(1); }
            else                   { CP_WAIT(0); }
            __syncthreads();

            unsigned int aBase = smem_u32 + buf * (AS_BYTES + BS_BYTES);
            unsigned int bBase = aBase + AS_BYTES;
#pragma unroll
            for (int kk = 0; kk < KC; kk += 16) {
                unsigned int a[2][4], b[4][4];
#pragma unroll
                for (int mt = 0; mt < 2; mt++) {
                    int r = wm * 32 + mt * 16 + (l & 15);
                    unsigned int addr = aBase + (r * APITCH + kk + 8 * (l >> 4)) * 2;
                    LDSM4(a[mt][0], a[mt][1], a[mt][2], a[mt][3], addr);
                }
#pragma unroll
                for (int bn = 0; bn < 4; bn++) {
                    int n = wn * 64 + bn * 16 + (l & 7) + ((l >> 4) & 1) * 8;
                    int k = kk + ((l >> 3) & 1) * 8;
                    unsigned int addr = bBase + (n * APITCH + k) * 2;
                    LDSM4(b[bn][0], b[bn][1], b[bn][2], b[bn][3], addr);
                }
#pragma unroll
                for (int mt = 0; mt < 2; mt++)
#pragma unroll
                    for (int nt = 0; nt < 8; nt++)
                        MMA16816(acc[mt][nt], a[mt],
                                 b[nt >> 1][(nt & 1) * 2], b[nt >> 1][(nt & 1) * 2 + 1]);
            }
            __syncthreads();
        }

        // epilogue: sign-weighted reduction of |z|^2 into y[8] per row (uniform 2^7 scale cancels).
        // col c = n0 + wn*64 + nt*8 + 2*(l&3) + e; k = c & 255.
        float yp[2][2][8];
#pragma unroll
        for (int mt = 0; mt < 2; mt++) {
#pragma unroll
            for (int half = 0; half < 2; half++) {
                float s0 = 0.f, T7 = 0.f, T4 = 0.f, T3 = 0.f, T2 = 0.f;
#pragma unroll
                for (int nt = 0; nt < 8; nt++) {
                    float v0 = acc[mt][nt][2 * half];
                    float v1 = acc[mt][nt][2 * half + 1];
                    float p1 = v1 * v1;
                    float ps = v0 * v0 + p1;
                    s0 += ps; T7 += p1;
                    if (nt & 1) T4 += ps;
                    if (nt & 2) T3 += ps;
                    if (nt & 4) T2 += ps;
                }
                yp[mt][half][7] = s0 - 2.f * T7;
                yp[mt][half][4] = s0 - 2.f * T4;
                yp[mt][half][3] = s0 - 2.f * T3;
                yp[mt][half][2] = s0 - 2.f * T2;
                yp[mt][half][6] = (l & 1) ? -s0 : s0;
                yp[mt][half][5] = (l & 2) ? -s0 : s0;
                yp[mt][half][1] = (wn & 1) ? -s0 : s0;
                yp[mt][half][0] = (wn & 2) ? -s0 : s0;
            }
        }
#pragma unroll
        for (int off = 1; off <= 2; off <<= 1)
#pragma unroll
            for (int mt = 0; mt < 2; mt++)
#pragma unroll
                for (int half = 0; half < 2; half++)
#pragma unroll
                    for (int ob = 0; ob < 8; ob++)
                        yp[mt][half][ob] += __shfl_xor_sync(0xffffffffu, yp[mt][half][ob], off);

        if ((l & 3) == 0) {
#pragma unroll
            for (int mt = 0; mt < 2; mt++)
#pragma unroll
                for (int half = 0; half < 2; half++) {
                    int r = wm * 32 + mt * 16 + half * 8 + (l >> 2);
                    float* dst = &ypart[((size_t)wn * BM + r) * 8];
                    if (nc == 0) {
#pragma unroll
                        for (int ob = 0; ob < 8; ob++) dst[ob] = yp[mt][half][ob];
                    } else {
#pragma unroll
                        for (int ob = 0; ob < 8; ob++) dst[ob] += yp[mt][half][ob];
                    }
                }
        }
        __syncthreads();
    }

    // reduce over wn partials
    for (int idx = tid; idx < BM * 8; idx += THREADS) {
        float v = ypart[idx] + ypart[BM * 8 + idx] + ypart[2 * BM * 8 + idx] + ypart[3 * BM * 8 + idx];
        ys[idx] = v;
    }
    __syncthreads();

    // output: out[row][c] = y_c^2 / sum(y^2) for c<8 else 0
    {
        int r = tid >> 2, q = tid & 3;
        float yv[8];
#pragma unroll
        for (int ob = 0; ob < 8; ob++) yv[ob] = ys[r * 8 + ob];
        float n2 = 0.f;
#pragma unroll
        for (int ob = 0; ob < 8; ob++) n2 += yv[ob] * yv[ob];
        float inv = 1.0f / fmaxf(n2, 1e-30f);
        float4* orow = reinterpret_cast<float4*>(out + (size_t)(row0 + r) * 256 + q * 64);
        float4 z4 = make_float4(0.f, 0.f, 0.f, 0.f);
#pragma unroll
        for (int j = 0; j < 16; j++) {
            float4 v = z4;
            if (q == 0 && j == 0)
                v = make_float4(yv[0]*yv[0]*inv, yv[1]*yv[1]*inv, yv[2]*yv[2]*inv, yv[3]*yv[3]*inv);
            else if (q == 0 && j == 1)
                v = make_float4(yv[4]*yv[4]*inv, yv[5]*yv[5]*inv, yv[6]*yv[6]*inv, yv[7]*yv[7]*inv);
            orow[j] = v;
        }
    }
}

extern "C" void kernel_launch(void* const* d_in, const int* in_sizes, int n_in,
                              void* d_out, int out_size) {
    const float* x   = (const float*)d_in[0];
    const float* th1 = (const float*)d_in[1];
    const float* th2 = (const float*)d_in[2];
    const float* th3 = (const float*)d_in[3];
    float* out = (float*)d_out;

    int nrows = in_sizes[0] / 256;   // 32768

    cudaFuncSetAttribute(pqc_mma_kernel,
                         cudaFuncAttributeMaxDynamicSharedMemorySize, SMEM_TOTAL);

    prep_build_kernel<<<256 + (nrows * 64) / 256, 256>>>(x, th1, th2, th3);
    pqc_mma_kernel<<<nrows / BM, THREADS, SMEM_TOTAL>>>(out);
}